// round 5
// baseline (speedup 1.0000x reference)
#include <cuda_runtime.h>
#include <cuda_fp16.h>
#include <cstdint>

#define N_NODES 50000
#define N_EDGES 800000
#define D 96
#define DH2 (D/2)   // 48 half2 per row
#define GR 64       // rows per GEMM block

// -------- scratch (static device globals; no allocation allowed) --------
__device__ __align__(16) __half g_xwh[N_NODES * D];  // X @ W, fp16 storage
__device__ __align__(16) float  g_h  [N_NODES * D];  // layer-1 output (fp32)
__device__ float g_dinv[N_NODES];                    // 1/sqrt(deg)
__device__ int   g_cnt [N_NODES];                    // in-degree histogram
__device__ int   g_cur [N_NODES];                    // fill cursors
__device__ int   g_rowptr[N_NODES + 1];              // CSR row pointers (by dst)
__device__ int   g_csr [N_EDGES];                    // CSR column indices (src)

#define FMA_F32X2(d, a, b, c) \
    asm("fma.rn.f32x2 %0, %1, %2, %3;" : "=l"(d) : "l"(a), "l"(b), "l"(c))
#define PACK_F32X2(out, lo, hi) \
    asm("mov.b64 %0, {%1, %2};" : "=l"(out) : "f"(lo), "f"(hi))
#define UNPACK_F32X2(lo, hi, in) \
    asm("mov.b64 {%0, %1}, %2;" : "=f"(lo), "=f"(hi) : "l"(in))

// ---------------- CSR build ----------------
__global__ void k_zero() {
    int i = blockIdx.x * blockDim.x + threadIdx.x;
    if (i < N_NODES) { g_cnt[i] = 0; g_cur[i] = 0; }
}

// 4 edges per thread -> 4 independent atomic chains (MLP)
__global__ void k_count(const int* __restrict__ dst) {
    int e = (blockIdx.x * blockDim.x + threadIdx.x) * 4;
    if (e + 3 < N_EDGES) {
        int d0 = dst[e], d1 = dst[e+1], d2 = dst[e+2], d3 = dst[e+3];
        atomicAdd(&g_cnt[d0], 1);
        atomicAdd(&g_cnt[d1], 1);
        atomicAdd(&g_cnt[d2], 1);
        atomicAdd(&g_cnt[d3], 1);
    } else {
        for (int k = e; k < N_EDGES; k++) atomicAdd(&g_cnt[dst[k]], 1);
    }
}

// single-CTA exclusive prefix scan over 50k bins (hierarchical); writes dinv
__global__ void __launch_bounds__(1024) k_scan() {
    __shared__ int wsum[32];
    const int T = 1024;
    const int CHUNK = (N_NODES + T - 1) / T;   // 49
    int t = threadIdx.x;
    int lane = t & 31, wid = t >> 5;
    int beg = t * CHUNK;
    int end = min(beg + CHUNK, N_NODES);
    if (beg > N_NODES) beg = N_NODES;
    if (end < beg) end = beg;

    int local = 0;
    for (int i = beg; i < end; i++) local += g_cnt[i];

    int v = local;
    #pragma unroll
    for (int off = 1; off < 32; off <<= 1) {
        int n = __shfl_up_sync(0xFFFFFFFFu, v, off);
        if (lane >= off) v += n;
    }
    if (lane == 31) wsum[wid] = v;
    __syncthreads();
    if (wid == 0) {
        int wv = wsum[lane];
        #pragma unroll
        for (int off = 1; off < 32; off <<= 1) {
            int n = __shfl_up_sync(0xFFFFFFFFu, wv, off);
            if (lane >= off) wv += n;
        }
        wsum[lane] = wv;
    }
    __syncthreads();

    int excl = v - local + (wid > 0 ? wsum[wid - 1] : 0);
    if (t == T - 1) g_rowptr[N_NODES] = excl + local;   // == N_EDGES

    int acc = excl;
    for (int i = beg; i < end; i++) {
        g_rowptr[i] = acc;
        int c = g_cnt[i];
        acc += c;
        g_dinv[i] = rsqrtf(1.0f + (float)c);
    }
}

// 4 edges per thread (MLP on the atomic cursors)
__global__ void k_fill(const int* __restrict__ src,
                       const int* __restrict__ dst) {
    int e = (blockIdx.x * blockDim.x + threadIdx.x) * 4;
    if (e + 3 < N_EDGES) {
        int d0 = dst[e], d1 = dst[e+1], d2 = dst[e+2], d3 = dst[e+3];
        int s0 = src[e], s1 = src[e+1], s2 = src[e+2], s3 = src[e+3];
        int p0 = g_rowptr[d0] + atomicAdd(&g_cur[d0], 1);
        int p1 = g_rowptr[d1] + atomicAdd(&g_cur[d1], 1);
        int p2 = g_rowptr[d2] + atomicAdd(&g_cur[d2], 1);
        int p3 = g_rowptr[d3] + atomicAdd(&g_cur[d3], 1);
        g_csr[p0] = s0; g_csr[p1] = s1; g_csr[p2] = s2; g_csr[p3] = s3;
    } else {
        for (int k = e; k < N_EDGES; k++) {
            int d = dst[k];
            int pos = g_rowptr[d] + atomicAdd(&g_cur[d], 1);
            g_csr[pos] = src[k];
        }
    }
}

// ---------------- GEMM: g_xwh[N,96] = fp16(X[N,96] @ W[96,96]) ----------------
// 64 rows / block, 256 threads, packed f32x2 accumulation (FFMA2).
__global__ void __launch_bounds__(256)
k_gemm(const float* __restrict__ Xext, const float* __restrict__ W, int use_h) {
    __shared__ float  Ws[D * D];                 // 36864 B
    __shared__ float2 Xp[D * (GR / 2)];          // 24576 B
    const float* __restrict__ X = use_h ? (const float*)g_h : Xext;

    int t = threadIdx.x;
    int rowBase = blockIdx.x * GR;

    for (int i = t; i < D * D; i += 256) Ws[i] = W[i];

    float* xpf = reinterpret_cast<float*>(Xp);
    for (int i = t; i < GR * (D / 4); i += 256) {
        int r  = i / (D / 4);
        int c4 = i % (D / 4);
        int row = rowBase + r;
        float4 v = (row < N_NODES)
            ? reinterpret_cast<const float4*>(X + (size_t)row * D)[c4]
            : make_float4(0.f, 0.f, 0.f, 0.f);
        int pair = r >> 1, half = r & 1;
        int k0 = c4 * 4;
        xpf[(k0 + 0) * GR + pair * 2 + half] = v.x;
        xpf[(k0 + 1) * GR + pair * 2 + half] = v.y;
        xpf[(k0 + 2) * GR + pair * 2 + half] = v.z;
        xpf[(k0 + 3) * GR + pair * 2 + half] = v.w;
    }
    __syncthreads();

    int ty = t >> 5, tx = t & 31;
    unsigned long long acc[4][3];
    #pragma unroll
    for (int p = 0; p < 4; p++)
        #pragma unroll
        for (int c = 0; c < 3; c++) acc[p][c] = 0ull;

    const unsigned long long* xp64 =
        reinterpret_cast<const unsigned long long*>(Xp);

    #pragma unroll 2
    for (int k = 0; k < D; k++) {
        float w0 = Ws[k * D + tx * 3 + 0];
        float w1 = Ws[k * D + tx * 3 + 1];
        float w2 = Ws[k * D + tx * 3 + 2];
        unsigned long long w0p, w1p, w2p;
        PACK_F32X2(w0p, w0, w0);
        PACK_F32X2(w1p, w1, w1);
        PACK_F32X2(w2p, w2, w2);
        #pragma unroll
        for (int p = 0; p < 4; p++) {
            unsigned long long xv = xp64[k * (GR / 2) + ty * 4 + p];
            FMA_F32X2(acc[p][0], xv, w0p, acc[p][0]);
            FMA_F32X2(acc[p][1], xv, w1p, acc[p][1]);
            FMA_F32X2(acc[p][2], xv, w2p, acc[p][2]);
        }
    }

    #pragma unroll
    for (int p = 0; p < 4; p++) {
        int row0 = rowBase + (ty * 4 + p) * 2;
        #pragma unroll
        for (int c = 0; c < 3; c++) {
            float lo, hi;
            UNPACK_F32X2(lo, hi, acc[p][c]);
            int col = tx * 3 + c;
            if (row0 < N_NODES)
                g_xwh[(size_t)row0 * D + col] = __float2half_rn(lo);
            if (row0 + 1 < N_NODES)
                g_xwh[(size_t)(row0 + 1) * D + col] = __float2half_rn(hi);
        }
    }
}

// ---------------- fused aggregate + bias + relu ----------------
// One warp per node. Rows are fp16: 48 half2 per row. Lane owns half2 col
// pairs {lane} and {32+lane | lane<16}. 1.5 transactions per gathered row.
__global__ void __launch_bounds__(256)
k_agg(const float* __restrict__ b, float* __restrict__ outExt, int to_h) {
    int warp = (blockIdx.x * blockDim.x + threadIdx.x) >> 5;
    int lane = threadIdx.x & 31;
    if (warp >= N_NODES) return;
    int i = warp;
    bool hasHi = lane < (DH2 - 32);   // lanes 0..15 own the second pair

    float di = g_dinv[i];
    const half2* __restrict__ pi =
        reinterpret_cast<const half2*>(g_xwh + (size_t)i * D);
    float2 f0 = __half22float2(pi[lane]);
    float2 f1 = hasHi ? __half22float2(pi[32 + lane]) : make_float2(0.f, 0.f);
    float2 a0 = make_float2(f0.x * di, f0.y * di);
    float2 a1 = make_float2(f1.x * di, f1.y * di);

    int beg = g_rowptr[i];
    int end = g_rowptr[i + 1];
    int j = beg;

    for (; j + 4 <= end; j += 4) {
        int s0 = g_csr[j + 0];
        int s1 = g_csr[j + 1];
        int s2 = g_csr[j + 2];
        int s3 = g_csr[j + 3];
        float w0 = g_dinv[s0], w1 = g_dinv[s1], w2 = g_dinv[s2], w3 = g_dinv[s3];
        const half2* __restrict__ p0 = reinterpret_cast<const half2*>(g_xwh + (size_t)s0 * D);
        const half2* __restrict__ p1 = reinterpret_cast<const half2*>(g_xwh + (size_t)s1 * D);
        const half2* __restrict__ p2 = reinterpret_cast<const half2*>(g_xwh + (size_t)s2 * D);
        const half2* __restrict__ p3 = reinterpret_cast<const half2*>(g_xwh + (size_t)s3 * D);
        half2 v00 = p0[lane], v10 = p1[lane], v20 = p2[lane], v30 = p3[lane];
        half2 v01 = make_half2(__float2half(0.f), __float2half(0.f));
        half2 v11 = v01, v21 = v01, v31 = v01;
        if (hasHi) {
            v01 = p0[32 + lane]; v11 = p1[32 + lane];
            v21 = p2[32 + lane]; v31 = p3[32 + lane];
        }
        float2 g00 = __half22float2(v00), g01 = __half22float2(v01);
        float2 g10 = __half22float2(v10), g11 = __half22float2(v11);
        float2 g20 = __half22float2(v20), g21 = __half22float2(v21);
        float2 g30 = __half22float2(v30), g31 = __half22float2(v31);
        a0.x += g00.x * w0; a0.y += g00.y * w0; a1.x += g01.x * w0; a1.y += g01.y * w0;
        a0.x += g10.x * w1; a0.y += g10.y * w1; a1.x += g11.x * w1; a1.y += g11.y * w1;
        a0.x += g20.x * w2; a0.y += g20.y * w2; a1.x += g21.x * w2; a1.y += g21.y * w2;
        a0.x += g30.x * w3; a0.y += g30.y * w3; a1.x += g31.x * w3; a1.y += g31.y * w3;
    }
    for (; j < end; j++) {
        int s = g_csr[j];
        float ws = g_dinv[s];
        const half2* __restrict__ ps = reinterpret_cast<const half2*>(g_xwh + (size_t)s * D);
        float2 g0 = __half22float2(ps[lane]);
        a0.x += g0.x * ws; a0.y += g0.y * ws;
        if (hasHi) {
            float2 g1 = __half22float2(ps[32 + lane]);
            a1.x += g1.x * ws; a1.y += g1.y * ws;
        }
    }

    float* __restrict__ out = to_h ? g_h : outExt;
    const float2* __restrict__ bp = reinterpret_cast<const float2*>(b);
    float2* __restrict__ op = reinterpret_cast<float2*>(out + (size_t)i * D);
    float2 bb0 = bp[lane];
    float2 r0;
    r0.x = fmaxf(a0.x * di + bb0.x, 0.0f);
    r0.y = fmaxf(a0.y * di + bb0.y, 0.0f);
    op[lane] = r0;
    if (hasHi) {
        float2 bb1 = bp[32 + lane];
        float2 r1;
        r1.x = fmaxf(a1.x * di + bb1.x, 0.0f);
        r1.y = fmaxf(a1.y * di + bb1.y, 0.0f);
        op[32 + lane] = r1;
    }
}

// ---------------- launch ----------------
extern "C" void kernel_launch(void* const* d_in, const int* in_sizes, int n_in,
                              void* d_out, int out_size) {
    const float* x   = (const float*)d_in[0];
    const int*   ei  = (const int*)d_in[1];   // [2, E] int32 (JAX x64 disabled)
    const float* W1  = (const float*)d_in[2];
    const float* b1  = (const float*)d_in[3];
    const float* W2  = (const float*)d_in[4];
    const float* b2  = (const float*)d_in[5];
    float*       out = (float*)d_out;

    const int* src = ei;
    const int* dst = ei + N_EDGES;

    const int T = 256;
    int gN    = (N_NODES + T - 1) / T;
    int gE4   = (N_EDGES / 4 + T - 1) / T;
    int gGemm = (N_NODES + GR - 1) / GR;
    int gAgg  = (N_NODES * 32 + T - 1) / T;   // warp per node

    // CSR build + norms (shared by both layers)
    k_zero  <<<gN, T>>>();
    k_count <<<gE4, T>>>(dst);
    k_scan  <<<1, 1024>>>();
    k_fill  <<<gE4, T>>>(src, dst);

    // layer 1: h = relu(agg(x @ W1) + b1)
    k_gemm <<<gGemm, T>>>(x, W1, 0);
    k_agg  <<<gAgg, T>>>(b1, out, 1);

    // layer 2: out = relu(agg(h @ W2) + b2)
    k_gemm <<<gGemm, T>>>(nullptr, W2, 1);
    k_agg  <<<gAgg, T>>>(b2, out, 0);
}

// round 6
// speedup vs baseline: 1.0189x; 1.0189x over previous
#include <cuda_runtime.h>
#include <cuda_bf16.h>
#include <cstdint>

#define N_NODES 50000
#define N_EDGES 800000
#define D 96
#define NF4 (D/4)   // 24 float4 per row
#define GR 64       // rows per GEMM block

// -------- scratch (static device globals; no allocation allowed) --------
__device__ __align__(16) float g_xw [N_NODES * D];   // X @ W (current layer)
__device__ __align__(16) float g_h  [N_NODES * D];   // layer-1 output
__device__ float g_dinv[N_NODES];                    // 1/sqrt(deg)
__device__ int   g_cnt [N_NODES];                    // in-degree histogram
__device__ int   g_cur [N_NODES];                    // fill cursors
__device__ int   g_rowptr[N_NODES + 1];              // CSR row pointers (by dst)
__device__ int   g_csr [N_EDGES];                    // CSR column indices (src)

#define FMA_F32X2(d, a, b, c) \
    asm("fma.rn.f32x2 %0, %1, %2, %3;" : "=l"(d) : "l"(a), "l"(b), "l"(c))
#define PACK_F32X2(out, lo, hi) \
    asm("mov.b64 %0, {%1, %2};" : "=l"(out) : "f"(lo), "f"(hi))
#define UNPACK_F32X2(lo, hi, in) \
    asm("mov.b64 {%0, %1}, %2;" : "=f"(lo), "=f"(hi) : "l"(in))

// ---------------- CSR build ----------------
__global__ void k_zero() {
    int i = blockIdx.x * blockDim.x + threadIdx.x;
    if (i < N_NODES) { g_cnt[i] = 0; g_cur[i] = 0; }
}

__global__ void k_count(const int* __restrict__ dst) {
    int e = blockIdx.x * blockDim.x + threadIdx.x;
    if (e < N_EDGES) atomicAdd(&g_cnt[dst[e]], 1);
}

// single-CTA exclusive prefix scan over 50k bins (hierarchical); writes dinv
__global__ void __launch_bounds__(1024) k_scan() {
    __shared__ int wsum[32];
    const int T = 1024;
    const int CHUNK = (N_NODES + T - 1) / T;   // 49
    int t = threadIdx.x;
    int lane = t & 31, wid = t >> 5;
    int beg = t * CHUNK;
    int end = min(beg + CHUNK, N_NODES);
    if (beg > N_NODES) beg = N_NODES;
    if (end < beg) end = beg;

    int local = 0;
    for (int i = beg; i < end; i++) local += g_cnt[i];

    int v = local;
    #pragma unroll
    for (int off = 1; off < 32; off <<= 1) {
        int n = __shfl_up_sync(0xFFFFFFFFu, v, off);
        if (lane >= off) v += n;
    }
    if (lane == 31) wsum[wid] = v;
    __syncthreads();
    if (wid == 0) {
        int wv = wsum[lane];
        #pragma unroll
        for (int off = 1; off < 32; off <<= 1) {
            int n = __shfl_up_sync(0xFFFFFFFFu, wv, off);
            if (lane >= off) wv += n;
        }
        wsum[lane] = wv;
    }
    __syncthreads();

    int excl = v - local + (wid > 0 ? wsum[wid - 1] : 0);
    if (t == T - 1) g_rowptr[N_NODES] = excl + local;   // == N_EDGES

    int acc = excl;
    for (int i = beg; i < end; i++) {
        g_rowptr[i] = acc;
        int c = g_cnt[i];
        acc += c;
        g_dinv[i] = rsqrtf(1.0f + (float)c);
    }
}

__global__ void k_fill(const int* __restrict__ src,
                       const int* __restrict__ dst) {
    int e = blockIdx.x * blockDim.x + threadIdx.x;
    if (e >= N_EDGES) return;
    int d = dst[e];
    int pos = g_rowptr[d] + atomicAdd(&g_cur[d], 1);
    g_csr[pos] = src[e];
}

// ---------------- GEMM: g_xw[N,96] = X[N,96] @ W[96,96] ----------------
// 64 rows / block, 256 threads, packed f32x2 accumulation (FFMA2).
__global__ void __launch_bounds__(256)
k_gemm(const float* __restrict__ Xext, const float* __restrict__ W, int use_h) {
    __shared__ float  Ws[D * D];                 // 36864 B
    __shared__ float2 Xp[D * (GR / 2)];          // 24576 B
    const float* __restrict__ X = use_h ? (const float*)g_h : Xext;

    int t = threadIdx.x;
    int rowBase = blockIdx.x * GR;

    for (int i = t; i < D * D; i += 256) Ws[i] = W[i];

    float* xpf = reinterpret_cast<float*>(Xp);
    for (int i = t; i < GR * (D / 4); i += 256) {
        int r  = i / (D / 4);
        int c4 = i % (D / 4);
        int row = rowBase + r;
        float4 v = (row < N_NODES)
            ? reinterpret_cast<const float4*>(X + (size_t)row * D)[c4]
            : make_float4(0.f, 0.f, 0.f, 0.f);
        int pair = r >> 1, half = r & 1;
        int k0 = c4 * 4;
        xpf[(k0 + 0) * GR + pair * 2 + half] = v.x;
        xpf[(k0 + 1) * GR + pair * 2 + half] = v.y;
        xpf[(k0 + 2) * GR + pair * 2 + half] = v.z;
        xpf[(k0 + 3) * GR + pair * 2 + half] = v.w;
    }
    __syncthreads();

    int ty = t >> 5, tx = t & 31;
    unsigned long long acc[4][3];
    #pragma unroll
    for (int p = 0; p < 4; p++)
        #pragma unroll
        for (int c = 0; c < 3; c++) acc[p][c] = 0ull;

    const unsigned long long* xp64 =
        reinterpret_cast<const unsigned long long*>(Xp);

    #pragma unroll 2
    for (int k = 0; k < D; k++) {
        float w0 = Ws[k * D + tx * 3 + 0];
        float w1 = Ws[k * D + tx * 3 + 1];
        float w2 = Ws[k * D + tx * 3 + 2];
        unsigned long long w0p, w1p, w2p;
        PACK_F32X2(w0p, w0, w0);
        PACK_F32X2(w1p, w1, w1);
        PACK_F32X2(w2p, w2, w2);
        #pragma unroll
        for (int p = 0; p < 4; p++) {
            unsigned long long xv = xp64[k * (GR / 2) + ty * 4 + p];
            FMA_F32X2(acc[p][0], xv, w0p, acc[p][0]);
            FMA_F32X2(acc[p][1], xv, w1p, acc[p][1]);
            FMA_F32X2(acc[p][2], xv, w2p, acc[p][2]);
        }
    }

    #pragma unroll
    for (int p = 0; p < 4; p++) {
        int row0 = rowBase + (ty * 4 + p) * 2;
        #pragma unroll
        for (int c = 0; c < 3; c++) {
            float lo, hi;
            UNPACK_F32X2(lo, hi, acc[p][c]);
            if (row0 < N_NODES)     g_xw[(size_t)row0 * D + tx * 3 + c] = lo;
            if (row0 + 1 < N_NODES) g_xw[(size_t)(row0 + 1) * D + tx * 3 + c] = hi;
        }
    }
}

// ---------------- fused aggregate + bias + relu ----------------
// 64-thread CTAs (2 warps = 2 nodes) for load balance: E[max of 2 Poisson]
// << E[max of 8]. Lanes 0..23 gather one float4 (row = 384B = 3 wavefronts,
// 1 LDG.128 issue). Edge loop unrolled 2x.
__global__ void __launch_bounds__(64)
k_agg(const float* __restrict__ b, float* __restrict__ outExt, int to_h) {
    int node = blockIdx.x * 2 + (threadIdx.x >> 5);
    int lane = threadIdx.x & 31;
    if (node >= N_NODES) return;
    bool act = lane < NF4;

    const float4* __restrict__ xw4 = reinterpret_cast<const float4*>(g_xw);
    float di = g_dinv[node];

    float4 a = make_float4(0.f, 0.f, 0.f, 0.f);
    if (act) {
        float4 v = xw4[(size_t)node * NF4 + lane];
        a.x = v.x * di; a.y = v.y * di; a.z = v.z * di; a.w = v.w * di;
    }

    int beg = g_rowptr[node];
    int end = g_rowptr[node + 1];
    int j = beg;

    for (; j + 2 <= end; j += 2) {
        int s0 = g_csr[j];
        int s1 = g_csr[j + 1];
        float w0 = g_dinv[s0];
        float w1 = g_dinv[s1];
        if (act) {
            float4 v0 = xw4[(size_t)s0 * NF4 + lane];
            float4 v1 = xw4[(size_t)s1 * NF4 + lane];
            a.x += v0.x * w0; a.y += v0.y * w0; a.z += v0.z * w0; a.w += v0.w * w0;
            a.x += v1.x * w1; a.y += v1.y * w1; a.z += v1.z * w1; a.w += v1.w * w1;
        }
    }
    if (j < end) {
        int s = g_csr[j];
        float ws = g_dinv[s];
        if (act) {
            float4 v = xw4[(size_t)s * NF4 + lane];
            a.x += v.x * ws; a.y += v.y * ws; a.z += v.z * ws; a.w += v.w * ws;
        }
    }

    if (act) {
        const float4* __restrict__ b4 = reinterpret_cast<const float4*>(b);
        float4 bb = b4[lane];
        float4 r;
        r.x = fmaxf(a.x * di + bb.x, 0.0f);
        r.y = fmaxf(a.y * di + bb.y, 0.0f);
        r.z = fmaxf(a.z * di + bb.z, 0.0f);
        r.w = fmaxf(a.w * di + bb.w, 0.0f);
        float4* __restrict__ op =
            reinterpret_cast<float4*>(to_h ? g_h : outExt);
        op[(size_t)node * NF4 + lane] = r;
    }
}

// ---------------- launch ----------------
extern "C" void kernel_launch(void* const* d_in, const int* in_sizes, int n_in,
                              void* d_out, int out_size) {
    const float* x   = (const float*)d_in[0];
    const int*   ei  = (const int*)d_in[1];   // [2, E] int32 (JAX x64 disabled)
    const float* W1  = (const float*)d_in[2];
    const float* b1  = (const float*)d_in[3];
    const float* W2  = (const float*)d_in[4];
    const float* b2  = (const float*)d_in[5];
    float*       out = (float*)d_out;

    const int* src = ei;
    const int* dst = ei + N_EDGES;

    const int T = 256;
    int gN    = (N_NODES + T - 1) / T;
    int gE    = (N_EDGES + T - 1) / T;
    int gGemm = (N_NODES + GR - 1) / GR;
    int gAgg  = (N_NODES + 1) / 2;            // 2 nodes (warps) per 64-thr CTA

    // CSR build + norms (shared by both layers)
    k_zero  <<<gN, T>>>();
    k_count <<<gE, T>>>(dst);
    k_scan  <<<1, 1024>>>();
    k_fill  <<<gE, T>>>(src, dst);

    // layer 1: h = relu(agg(x @ W1) + b1)
    k_gemm <<<gGemm, T>>>(x, W1, 0);
    k_agg  <<<gAgg, 64>>>(b1, out, 1);

    // layer 2: out = relu(agg(h @ W2) + b2)
    k_gemm <<<gGemm, T>>>(nullptr, W2, 1);
    k_agg  <<<gAgg, 64>>>(b2, out, 0);
}